// round 3
// baseline (speedup 1.0000x reference)
#include <cuda_runtime.h>
#include <math.h>

// dims
#define Bq 16
#define Tt 120
#define Nj 24
#define Dd 256
#define Hh 8
#define DPp 32
#define TOT (Bq*Tt*Nj*Dd)   // 11,796,480
#define LDJ (Nj*Dd)         // 6144

// scratch buffers (static device memory is allowed; cudaMalloc is not)
__device__ float g_qt[TOT];
__device__ float g_kt[TOT];
__device__ float g_vt[TOT];
__device__ float g_qs[TOT];
__device__ float g_ks[TOT];
__device__ float g_vs[TOT];
__device__ float g_ta[TOT];
__device__ float g_sa[TOT];
__device__ float g_to[TOT];
__device__ float g_y[TOT];
__device__ float g_h[TOT];

// ---------------------------------------------------------------------------
// Generic tiled GEMM: C = A @ W + bias with fused epilogues.
// K = 256, Nout = 256 fixed. M divisible by 64. blockIdx.z = joint.
// epi: 0 = bias, 1 = bias+relu, 2 = bias + R1, 3 = bias + R1 + R2
// ---------------------------------------------------------------------------
__global__ void __launch_bounds__(256) gemm256(
    const float* __restrict__ A, int ldA, int aJ,
    const float* __restrict__ W, int wJ,
    const float* __restrict__ bias, int bJ,
    float* __restrict__ C, int ldC, int cJ,
    const float* __restrict__ R1, const float* __restrict__ R2,
    int epi)
{
    __shared__ float As[16][65];
    __shared__ float Ws[16][65];

    const int j = blockIdx.z;
    const float* Ab = A + (size_t)j * aJ;
    const float* Wb = W + (size_t)j * wJ;
    const float* bb = bias + (size_t)j * bJ;
    float* Cb = C + (size_t)j * cJ;
    const float* R1b = R1 ? (R1 + (size_t)j * cJ) : nullptr;
    const float* R2b = R2 ? (R2 + (size_t)j * cJ) : nullptr;

    const int row0 = blockIdx.x * 64;
    const int n0   = blockIdx.y * 64;
    const int tid = threadIdx.x;
    const int tx = tid & 15;
    const int ty = tid >> 4;

    // load mappings
    const int ka = tid & 15;         // k within A tile
    const int ma = tid >> 4;         // base row within A tile (16 rows / pass)
    const int nw = tid & 63;         // col within W tile
    const int kw = tid >> 6;         // base k within W tile (4 rows / pass)

    float acc[4][4];
#pragma unroll
    for (int i = 0; i < 4; i++)
#pragma unroll
        for (int q = 0; q < 4; q++) acc[i][q] = 0.f;

    for (int k0 = 0; k0 < 256; k0 += 16) {
#pragma unroll
        for (int i = 0; i < 4; i++)
            As[ka][ma + 16 * i] = Ab[(size_t)(row0 + ma + 16 * i) * ldA + k0 + ka];
#pragma unroll
        for (int i = 0; i < 4; i++)
            Ws[kw + 4 * i][nw] = Wb[(size_t)(k0 + kw + 4 * i) * 256 + n0 + nw];
        __syncthreads();

#pragma unroll
        for (int kk = 0; kk < 16; kk++) {
            float a[4], b[4];
#pragma unroll
            for (int i = 0; i < 4; i++) {
                a[i] = As[kk][ty + 16 * i];
                b[i] = Ws[kk][tx + 16 * i];
            }
#pragma unroll
            for (int i = 0; i < 4; i++)
#pragma unroll
                for (int q = 0; q < 4; q++)
                    acc[i][q] += a[i] * b[q];
        }
        __syncthreads();
    }

#pragma unroll
    for (int i = 0; i < 4; i++) {
        const int m = row0 + ty + 16 * i;
#pragma unroll
        for (int q = 0; q < 4; q++) {
            const int nn = n0 + tx + 16 * q;
            float v = acc[i][q] + bb[nn];
            const size_t off = (size_t)m * ldC + nn;
            if (epi == 1) v = fmaxf(v, 0.f);
            if (epi >= 2) v += R1b[off];
            if (epi == 3) v += R2b[off];
            Cb[off] = v;
        }
    }
}

// ---------------------------------------------------------------------------
// Temporal attention: one block per (b, n, h). Causal, with relative-position
// key/value embeddings. q row held in registers; K/V + rel tables in smem.
// ---------------------------------------------------------------------------
__global__ void __launch_bounds__(128) temporal_attn(
    const float* __restrict__ q, const float* __restrict__ k,
    const float* __restrict__ v,
    const float* __restrict__ relk, const float* __restrict__ relv,
    float* __restrict__ out)
{
    __shared__ float ks[Tt][DPp];
    __shared__ float vs[Tt][DPp];
    __shared__ float rk[33][DPp];
    __shared__ float rv[33][DPp];

    const int bid = blockIdx.x;
    const int b = bid / (Nj * Hh);
    const int rem = bid % (Nj * Hh);
    const int n = rem / Hh;
    const int h = rem % Hh;
    const int tid = threadIdx.x;

    const size_t base = ((size_t)b * Tt * Nj + n) * Dd + h * DPp;  // t stride = LDJ

    // load K, V (float4 vectorized: 120*8 float4 each)
    {
        const float4* k4 = reinterpret_cast<const float4*>(k);
        const float4* v4 = reinterpret_cast<const float4*>(v);
        for (int idx = tid; idx < Tt * 8; idx += 128) {
            const int t = idx >> 3, c = idx & 7;
            const size_t g = (base + (size_t)t * LDJ) / 4 + c;
            reinterpret_cast<float4*>(&ks[t][0])[c] = k4[g];
            reinterpret_cast<float4*>(&vs[t][0])[c] = v4[g];
        }
        const float4* rk4 = reinterpret_cast<const float4*>(relk);
        const float4* rv4 = reinterpret_cast<const float4*>(relv);
        for (int idx = tid; idx < 33 * 8; idx += 128) {
            reinterpret_cast<float4*>(&rk[0][0])[idx] = rk4[idx];
            reinterpret_cast<float4*>(&rv[0][0])[idx] = rv4[idx];
        }
    }
    __syncthreads();

    const int t = tid;
    if (t < Tt) {
        float qreg[DPp];
        {
            const float4* q4 = reinterpret_cast<const float4*>(q + base + (size_t)t * LDJ);
#pragma unroll
            for (int i = 0; i < 8; i++) {
                float4 vq = q4[i];
                qreg[4 * i + 0] = vq.x; qreg[4 * i + 1] = vq.y;
                qreg[4 * i + 2] = vq.z; qreg[4 * i + 3] = vq.w;
            }
        }
        // q projected onto the 33 causal relative keys
        float pr[33];
        for (int jj = 0; jj < 33; jj++) {
            float s = 0.f;
#pragma unroll
            for (int d = 0; d < DPp; d++) s += qreg[d] * rk[jj][d];
            pr[jj] = s;
        }

        const float scale = 0.17677669529663687f;  // 1/sqrt(32)
        float prob[Tt];
        float mx = -1e30f;
        for (int s = 0; s < Tt; s++) {
            float dot = 0.f;
#pragma unroll
            for (int d = 0; d < DPp; d++) dot += qreg[d] * ks[s][d];
            int jj = s - t + 32;
            if (jj < 0) jj = 0;
            if (jj > 32) jj = 32;
            const float lg = (s <= t) ? (dot + pr[jj]) * scale : -1e30f;
            prob[s] = lg;
            mx = fmaxf(mx, lg);
        }
        float sum = 0.f;
        for (int s = 0; s < Tt; s++) {
            const float e = __expf(prob[s] - mx);
            prob[s] = e;
            sum += e;
        }
        const float inv = 1.f / sum;
        float wsum[33];
        for (int jj = 0; jj < 33; jj++) wsum[jj] = 0.f;
        for (int s = 0; s < Tt; s++) {
            prob[s] *= inv;
            int jj = s - t + 32;
            if (jj < 0) jj = 0;
            if (jj > 32) jj = 32;
            wsum[jj] += prob[s];  // prob==0 for masked s, harmless
        }
        for (int d = 0; d < DPp; d++) {
            float acc = 0.f;
            for (int s = 0; s < Tt; s++) acc += prob[s] * vs[s][d];
            for (int jj = 0; jj < 33; jj++) acc += wsum[jj] * rv[jj][d];
            out[base + (size_t)t * LDJ + d] = acc;
        }
    }
}

// ---------------------------------------------------------------------------
// Spatial attention: one block (1 warp) per (b*t, h). 24 joints, no mask.
// ---------------------------------------------------------------------------
__global__ void __launch_bounds__(32) spatial_attn(
    const float* __restrict__ q, const float* __restrict__ k,
    const float* __restrict__ v, float* __restrict__ out)
{
    __shared__ float ks[Nj][DPp];
    __shared__ float vs[Nj][DPp];

    const int bid = blockIdx.x;       // B*T*H
    const int bt = bid / Hh;
    const int h = bid % Hh;
    const size_t base = (size_t)bt * LDJ + h * DPp;  // joint stride = Dd
    const int tid = threadIdx.x;

    {
        const float4* k4 = reinterpret_cast<const float4*>(k);
        const float4* v4 = reinterpret_cast<const float4*>(v);
        for (int idx = tid; idx < Nj * 8; idx += 32) {
            const int nn = idx >> 3, c = idx & 7;
            const size_t g = (base + (size_t)nn * Dd) / 4 + c;
            reinterpret_cast<float4*>(&ks[nn][0])[c] = k4[g];
            reinterpret_cast<float4*>(&vs[nn][0])[c] = v4[g];
        }
    }
    __syncwarp();

    const int nn = tid;
    if (nn < Nj) {
        float qreg[DPp];
        {
            const float4* q4 = reinterpret_cast<const float4*>(q + base + (size_t)nn * Dd);
#pragma unroll
            for (int i = 0; i < 8; i++) {
                float4 vq = q4[i];
                qreg[4 * i + 0] = vq.x; qreg[4 * i + 1] = vq.y;
                qreg[4 * i + 2] = vq.z; qreg[4 * i + 3] = vq.w;
            }
        }
        const float scale = 0.17677669529663687f;
        float prob[Nj];
        float mx = -1e30f;
        for (int m = 0; m < Nj; m++) {
            float dot = 0.f;
#pragma unroll
            for (int d = 0; d < DPp; d++) dot += qreg[d] * ks[m][d];
            dot *= scale;
            prob[m] = dot;
            mx = fmaxf(mx, dot);
        }
        float sum = 0.f;
        for (int m = 0; m < Nj; m++) {
            const float e = __expf(prob[m] - mx);
            prob[m] = e;
            sum += e;
        }
        const float inv = 1.f / sum;
        for (int m = 0; m < Nj; m++) prob[m] *= inv;
        for (int d = 0; d < DPp; d++) {
            float acc = 0.f;
            for (int m = 0; m < Nj; m++) acc += prob[m] * vs[m][d];
            out[base + (size_t)nn * Dd + d] = acc;
        }
    }
}

// ---------------------------------------------------------------------------
extern "C" void kernel_launch(void* const* d_in, const int* in_sizes, int n_in,
                              void* d_out, int out_size)
{
    const float* x     = (const float*)d_in[0];
    // d_in[1] = mask (causal handled analytically)
    const float* wq_t  = (const float*)d_in[2];
    const float* wk_t  = (const float*)d_in[3];
    const float* wv_t  = (const float*)d_in[4];
    const float* bq_t  = (const float*)d_in[5];
    const float* bk_t  = (const float*)d_in[6];
    const float* bv_t  = (const float*)d_in[7];
    const float* wo_t  = (const float*)d_in[8];
    const float* bo_t  = (const float*)d_in[9];
    const float* relk  = (const float*)d_in[10];
    const float* relv  = (const float*)d_in[11];
    const float* wq_s  = (const float*)d_in[12];
    const float* wk_s  = (const float*)d_in[13];
    const float* wv_s  = (const float*)d_in[14];
    const float* wo_s  = (const float*)d_in[15];
    const float* bq_s  = (const float*)d_in[16];
    const float* bk_s  = (const float*)d_in[17];
    const float* bv_s  = (const float*)d_in[18];
    const float* bo_s  = (const float*)d_in[19];
    const float* ff1w  = (const float*)d_in[20];
    const float* ff1b  = (const float*)d_in[21];
    const float* ff2w  = (const float*)d_in[22];
    const float* ff2b  = (const float*)d_in[23];
    float* out = (float*)d_out;

    float *qt, *kt, *vt, *qs, *ks_, *vs, *ta, *sa, *to, *y, *hh;
    cudaGetSymbolAddress((void**)&qt,  g_qt);
    cudaGetSymbolAddress((void**)&kt,  g_kt);
    cudaGetSymbolAddress((void**)&vt,  g_vt);
    cudaGetSymbolAddress((void**)&qs,  g_qs);
    cudaGetSymbolAddress((void**)&ks_, g_ks);
    cudaGetSymbolAddress((void**)&vs,  g_vs);
    cudaGetSymbolAddress((void**)&ta,  g_ta);
    cudaGetSymbolAddress((void**)&sa,  g_sa);
    cudaGetSymbolAddress((void**)&to,  g_to);
    cudaGetSymbolAddress((void**)&y,   g_y);
    cudaGetSymbolAddress((void**)&hh,  g_h);

    const dim3 gJ(30, 4, 24);    // per-joint GEMMs: M=1920 per joint
    const dim3 gC(720, 4, 1);    // contiguous GEMMs: M=46080

    // temporal QKV (per-joint weights)
    gemm256<<<gJ, 256>>>(x, LDJ, Dd, wq_t, Dd * Dd, bq_t, Dd, qt, LDJ, Dd, nullptr, nullptr, 0);
    gemm256<<<gJ, 256>>>(x, LDJ, Dd, wk_t, Dd * Dd, bk_t, Dd, kt, LDJ, Dd, nullptr, nullptr, 0);
    gemm256<<<gJ, 256>>>(x, LDJ, Dd, wv_t, Dd * Dd, bv_t, Dd, vt, LDJ, Dd, nullptr, nullptr, 0);
    // spatial QKV (shared weights)
    gemm256<<<gC, 256>>>(x, Dd, 0, wq_s, 0, bq_s, 0, qs, Dd, 0, nullptr, nullptr, 0);
    gemm256<<<gC, 256>>>(x, Dd, 0, wk_s, 0, bk_s, 0, ks_, Dd, 0, nullptr, nullptr, 0);
    gemm256<<<gC, 256>>>(x, Dd, 0, wv_s, 0, bv_s, 0, vs, Dd, 0, nullptr, nullptr, 0);

    temporal_attn<<<Bq * Nj * Hh, 128>>>(qt, kt, vt, relk, relv, ta);
    spatial_attn<<<Bq * Tt * Hh, 32>>>(qs, ks_, vs, sa);

    // output projections; wo_s epilogue fuses y = x + t_out + s_out
    gemm256<<<gC, 256>>>(ta, Dd, 0, wo_t, 0, bo_t, 0, to, Dd, 0, nullptr, nullptr, 0);
    gemm256<<<gC, 256>>>(sa, Dd, 0, wo_s, 0, bo_s, 0, y, Dd, 0, x, to, 3);

    // per-joint FFN; ff2 epilogue fuses the residual and writes final output
    gemm256<<<gJ, 256>>>(y, LDJ, Dd, ff1w, Dd * Dd, ff1b, Dd, hh, LDJ, Dd, nullptr, nullptr, 1);
    gemm256<<<gJ, 256>>>(hh, LDJ, Dd, ff2w, Dd * Dd, ff2b, Dd, out, LDJ, Dd, y, nullptr, 2);
}